// round 2
// baseline (speedup 1.0000x reference)
#include <cuda_runtime.h>

#define N_HID     128
#define N_ETYPES  10
#define N_EDGES   100000
#define TOTAL_EDGES (N_ETYPES * N_EDGES)

// One warp per edge. Each lane owns 4 consecutive dims (one float4).
// h gathers are coalesced 512B transactions; h (51MB) is L2-resident on GB300.
// Index arrays are int32 (JAX downcasts int64 without x64 mode).
__global__ void __launch_bounds__(256) distmult_kernel(
    const float* __restrict__ h,
    const float* __restrict__ W,
    const int* __restrict__ src,
    const int* __restrict__ dst,
    const int* __restrict__ rel,
    float* __restrict__ out)
{
    const int warp = (blockIdx.x * blockDim.x + threadIdx.x) >> 5;
    const int lane = threadIdx.x & 31;
    if (warp >= TOTAL_EDGES) return;

    const int t = warp / N_EDGES;                 // etype
    const int s = __ldg(&src[warp]);
    const int d = __ldg(&dst[warp]);
    const int r = __ldg(&rel[t]);

    const float4 a = __ldg((const float4*)(h + (long long)s * N_HID) + lane);
    const float4 w = __ldg((const float4*)(W + r * N_HID) + lane);
    const float4 b = __ldg((const float4*)(h + (long long)d * N_HID) + lane);

    float acc = a.x * w.x * b.x;
    acc = fmaf(a.y * w.y, b.y, acc);
    acc = fmaf(a.z * w.z, b.z, acc);
    acc = fmaf(a.w * w.w, b.w, acc);

    // warp reduction
    #pragma unroll
    for (int off = 16; off > 0; off >>= 1)
        acc += __shfl_xor_sync(0xffffffffu, acc, off);

    if (lane == 0)
        out[warp] = 1.0f / (1.0f + __expf(-acc));
}

extern "C" void kernel_launch(void* const* d_in, const int* in_sizes, int n_in,
                              void* d_out, int out_size)
{
    const float* h   = (const float*)d_in[0];   // [N_NODES, 128]
    const float* W   = (const float*)d_in[1];   // [10, 128]
    const int*   src = (const int*)d_in[2];     // [10, 100000] int32
    const int*   dst = (const int*)d_in[3];     // [10, 100000] int32
    const int*   rel = (const int*)d_in[4];     // [10] int32
    float* out = (float*)d_out;                 // [10, 100000]

    const int threads = 256;                    // 8 warps/block
    const long long total_threads = (long long)TOTAL_EDGES * 32;
    const int blocks = (int)((total_threads + threads - 1) / threads);
    distmult_kernel<<<blocks, threads>>>(h, W, src, dst, rel, out);
}

// round 3
// speedup vs baseline: 1.4851x; 1.4851x over previous
#include <cuda_runtime.h>

#define N_HID     128
#define N_ETYPES  10
#define N_EDGES   100000
#define TOTAL_EDGES (N_ETYPES * N_EDGES)
#define EPW       4   // edges per warp

// One warp per 4 consecutive edges. Each lane owns 4 dims (float4) of each edge.
// 8 independent 512B gathers in flight per warp (MLP=8); 4 interleaved shuffle
// reductions; one float4 store. h (51MB) is L2-resident; indices via int4.
__global__ void __launch_bounds__(256) distmult_kernel(
    const float* __restrict__ h,
    const float* __restrict__ W,
    const int* __restrict__ src,
    const int* __restrict__ dst,
    const int* __restrict__ rel,
    float* __restrict__ out)
{
    const int warp = (blockIdx.x * blockDim.x + threadIdx.x) >> 5;
    const int lane = threadIdx.x & 31;
    const int e0 = warp * EPW;
    if (e0 >= TOTAL_EDGES) return;

    const int t = e0 / N_EDGES;                 // all 4 edges same etype (100000 % 4 == 0)
    const int r = __ldg(&rel[t]);

    const int4 s4 = __ldg((const int4*)(src + e0));
    const int4 d4 = __ldg((const int4*)(dst + e0));

    const float4 w = __ldg((const float4*)(W + r * N_HID) + lane);

    // 8 independent gathers — issue all before consuming any
    const float4 a0 = __ldg((const float4*)(h + (size_t)s4.x * N_HID) + lane);
    const float4 a1 = __ldg((const float4*)(h + (size_t)s4.y * N_HID) + lane);
    const float4 a2 = __ldg((const float4*)(h + (size_t)s4.z * N_HID) + lane);
    const float4 a3 = __ldg((const float4*)(h + (size_t)s4.w * N_HID) + lane);
    const float4 b0 = __ldg((const float4*)(h + (size_t)d4.x * N_HID) + lane);
    const float4 b1 = __ldg((const float4*)(h + (size_t)d4.y * N_HID) + lane);
    const float4 b2 = __ldg((const float4*)(h + (size_t)d4.z * N_HID) + lane);
    const float4 b3 = __ldg((const float4*)(h + (size_t)d4.w * N_HID) + lane);

    float acc0 = a0.x * w.x * b0.x;
    acc0 = fmaf(a0.y * w.y, b0.y, acc0);
    acc0 = fmaf(a0.z * w.z, b0.z, acc0);
    acc0 = fmaf(a0.w * w.w, b0.w, acc0);

    float acc1 = a1.x * w.x * b1.x;
    acc1 = fmaf(a1.y * w.y, b1.y, acc1);
    acc1 = fmaf(a1.z * w.z, b1.z, acc1);
    acc1 = fmaf(a1.w * w.w, b1.w, acc1);

    float acc2 = a2.x * w.x * b2.x;
    acc2 = fmaf(a2.y * w.y, b2.y, acc2);
    acc2 = fmaf(a2.z * w.z, b2.z, acc2);
    acc2 = fmaf(a2.w * w.w, b2.w, acc2);

    float acc3 = a3.x * w.x * b3.x;
    acc3 = fmaf(a3.y * w.y, b3.y, acc3);
    acc3 = fmaf(a3.z * w.z, b3.z, acc3);
    acc3 = fmaf(a3.w * w.w, b3.w, acc3);

    // 4 independent butterfly reductions, interleaved for pipelining
    #pragma unroll
    for (int off = 16; off > 0; off >>= 1) {
        acc0 += __shfl_xor_sync(0xffffffffu, acc0, off);
        acc1 += __shfl_xor_sync(0xffffffffu, acc1, off);
        acc2 += __shfl_xor_sync(0xffffffffu, acc2, off);
        acc3 += __shfl_xor_sync(0xffffffffu, acc3, off);
    }

    if (lane == 0) {
        float4 o;
        o.x = 1.0f / (1.0f + __expf(-acc0));
        o.y = 1.0f / (1.0f + __expf(-acc1));
        o.z = 1.0f / (1.0f + __expf(-acc2));
        o.w = 1.0f / (1.0f + __expf(-acc3));
        *(float4*)(out + e0) = o;
    }
}

extern "C" void kernel_launch(void* const* d_in, const int* in_sizes, int n_in,
                              void* d_out, int out_size)
{
    const float* h   = (const float*)d_in[0];   // [N_NODES, 128]
    const float* W   = (const float*)d_in[1];   // [10, 128]
    const int*   src = (const int*)d_in[2];     // [10, 100000] int32
    const int*   dst = (const int*)d_in[3];     // [10, 100000] int32
    const int*   rel = (const int*)d_in[4];     // [10] int32
    float* out = (float*)d_out;                 // [10, 100000]

    const int threads = 256;                    // 8 warps/block, 32 edges/block
    const int warps_needed = TOTAL_EDGES / EPW; // 250000
    const int blocks = (warps_needed * 32 + threads - 1) / threads;
    distmult_kernel<<<blocks, threads>>>(h, W, src, dst, rel, out);
}

// round 4
// speedup vs baseline: 1.7591x; 1.1845x over previous
#include <cuda_runtime.h>

#define N_HID     128
#define N_ETYPES  10
#define N_EDGES   100000
#define TOTAL_EDGES (N_ETYPES * N_EDGES)
#define EPW       8   // edges per warp

// One warp per 8 consecutive edges. Each lane owns 4 dims (float4) of each edge.
// 16 independent 512B gathers in flight (MLP=16). Grouped shuffle reduction:
// 22 SHFLs per 8 edges instead of 40. h (51MB) is L2-resident.
__global__ void __launch_bounds__(128) distmult_kernel(
    const float* __restrict__ h,
    const float* __restrict__ W,
    const int* __restrict__ src,
    const int* __restrict__ dst,
    const int* __restrict__ rel,
    float* __restrict__ out)
{
    const int warp = (blockIdx.x * blockDim.x + threadIdx.x) >> 5;
    const int lane = threadIdx.x & 31;
    const int e0 = warp * EPW;
    if (e0 >= TOTAL_EDGES) return;

    const int t = e0 / N_EDGES;            // 100000 % 8 == 0: no etype straddle
    const int r = __ldg(&rel[t]);

    const int4 sA = __ldg((const int4*)(src + e0));
    const int4 sB = __ldg((const int4*)(src + e0 + 4));
    const int4 dA = __ldg((const int4*)(dst + e0));
    const int4 dB = __ldg((const int4*)(dst + e0 + 4));

    const float4 w = __ldg((const float4*)(W + r * N_HID) + lane);

    // 16 independent gathers — issue all before consuming any
    const float4 a0 = __ldg((const float4*)(h + (size_t)sA.x * N_HID) + lane);
    const float4 a1 = __ldg((const float4*)(h + (size_t)sA.y * N_HID) + lane);
    const float4 a2 = __ldg((const float4*)(h + (size_t)sA.z * N_HID) + lane);
    const float4 a3 = __ldg((const float4*)(h + (size_t)sA.w * N_HID) + lane);
    const float4 a4 = __ldg((const float4*)(h + (size_t)sB.x * N_HID) + lane);
    const float4 a5 = __ldg((const float4*)(h + (size_t)sB.y * N_HID) + lane);
    const float4 a6 = __ldg((const float4*)(h + (size_t)sB.z * N_HID) + lane);
    const float4 a7 = __ldg((const float4*)(h + (size_t)sB.w * N_HID) + lane);
    const float4 b0 = __ldg((const float4*)(h + (size_t)dA.x * N_HID) + lane);
    const float4 b1 = __ldg((const float4*)(h + (size_t)dA.y * N_HID) + lane);
    const float4 b2 = __ldg((const float4*)(h + (size_t)dA.z * N_HID) + lane);
    const float4 b3 = __ldg((const float4*)(h + (size_t)dA.w * N_HID) + lane);
    const float4 b4 = __ldg((const float4*)(h + (size_t)dB.x * N_HID) + lane);
    const float4 b5 = __ldg((const float4*)(h + (size_t)dB.y * N_HID) + lane);
    const float4 b6 = __ldg((const float4*)(h + (size_t)dB.z * N_HID) + lane);
    const float4 b7 = __ldg((const float4*)(h + (size_t)dB.w * N_HID) + lane);

#define DOT(acc, a, b)                    \
    float acc = a.x * w.x * b.x;          \
    acc = fmaf(a.y * w.y, b.y, acc);      \
    acc = fmaf(a.z * w.z, b.z, acc);      \
    acc = fmaf(a.w * w.w, b.w, acc);

    DOT(acc0, a0, b0) DOT(acc1, a1, b1) DOT(acc2, a2, b2) DOT(acc3, a3, b3)
    DOT(acc4, a4, b4) DOT(acc5, a5, b5) DOT(acc6, a6, b6) DOT(acc7, a7, b7)
#undef DOT

    // Stage 1: butterfly offsets 16, 8 on all 8 accs.
    // After this, acc_k[lane] depends only on (lane & 7).
    #pragma unroll
    for (int off = 16; off >= 8; off >>= 1) {
        acc0 += __shfl_xor_sync(0xffffffffu, acc0, off);
        acc1 += __shfl_xor_sync(0xffffffffu, acc1, off);
        acc2 += __shfl_xor_sync(0xffffffffu, acc2, off);
        acc3 += __shfl_xor_sync(0xffffffffu, acc3, off);
        acc4 += __shfl_xor_sync(0xffffffffu, acc4, off);
        acc5 += __shfl_xor_sync(0xffffffffu, acc5, off);
        acc6 += __shfl_xor_sync(0xffffffffu, acc6, off);
        acc7 += __shfl_xor_sync(0xffffffffu, acc7, off);
    }

    // Stage 2: each lane-octet g = lane>>3 adopts acc_g (and acc_{g+4}),
    // then butterflies within the octet to finish the 8-residue sum.
    const int g = lane >> 3;
    float selA = (g == 0) ? acc0 : (g == 1) ? acc1 : (g == 2) ? acc2 : acc3;
    float selB = (g == 0) ? acc4 : (g == 1) ? acc5 : (g == 2) ? acc6 : acc7;
    #pragma unroll
    for (int off = 4; off > 0; off >>= 1) {
        selA += __shfl_xor_sync(0xffffffffu, selA, off);
        selB += __shfl_xor_sync(0xffffffffu, selB, off);
    }

    if ((lane & 7) == 0) {
        out[e0 + g]     = 1.0f / (1.0f + __expf(-selA));
        out[e0 + 4 + g] = 1.0f / (1.0f + __expf(-selB));
    }
}

extern "C" void kernel_launch(void* const* d_in, const int* in_sizes, int n_in,
                              void* d_out, int out_size)
{
    const float* h   = (const float*)d_in[0];   // [N_NODES, 128]
    const float* W   = (const float*)d_in[1];   // [10, 128]
    const int*   src = (const int*)d_in[2];     // [10, 100000] int32
    const int*   dst = (const int*)d_in[3];     // [10, 100000] int32
    const int*   rel = (const int*)d_in[4];     // [10] int32
    float* out = (float*)d_out;                 // [10, 100000]

    const int threads = 128;                    // 4 warps/block, 32 edges/block
    const int warps_needed = TOTAL_EDGES / EPW; // 125000
    const int blocks = (warps_needed * 32 + threads - 1) / threads;
    distmult_kernel<<<blocks, threads>>>(h, W, src, dst, rel, out);
}